// round 16
// baseline (speedup 1.0000x reference)
#include <cuda_runtime.h>
#include <cuda_fp16.h>

typedef unsigned long long u64;
typedef unsigned int u32;

#define Nn   200000
#define Ee   3200000
#define Bb   512
#define EMB  32
#define HID  64
#define TILE 1024
#define NT   ((Nn + TILE - 1) / TILE)   // 196 scan tiles
#define NUB  ((Nn + 255) / 256)         // update blocks

// ---------------- scratch (device globals) ----------------
__device__ uint4 g_h0h [Nn * 4];          // 12.8 MB fp16 h0 (32 ch)
__device__ uint4 g_ag1h[Nn * 4];          // 12.8 MB fp16 agg1
__device__ uint4 g_h1h [Nn * 8];          // 25.6 MB fp16 h1 (64 ch)
__device__ uint4 g_ag2h[Nn * 8];          // 25.6 MB fp16 agg2
__device__ int   g_csr [Ee];
__device__ __align__(16) int g_rank[Ee];
__device__ int   g_rowptr[Nn];
__device__ int   g_deg [Nn];
__device__ float g_dinv[Nn];
__device__ float g_hg  [Bb * HID];
__device__ int   g_gfirst[Bb];
__device__ int   g_glast [Bb];
__device__ volatile unsigned g_tilest[NT];
__device__ int   g_ticket;

// ---------------- helpers ----------------
__device__ __forceinline__ void red2(float* p, float x, float y) {
    asm volatile("red.global.add.v2.f32 [%0], {%1,%2};"
                 :: "l"(p), "f"(x), "f"(y) : "memory");
}
__device__ __forceinline__ unsigned ph2(float a, float b) {
    __half2 h = __floats2half2_rn(a, b); return *(unsigned*)&h;
}
__device__ __forceinline__ void mma16816(float& c0, float& c1, float& c2, float& c3,
                                         u32 a0, u32 a1, u32 a2, u32 a3,
                                         u32 b0, u32 b1) {
    asm volatile("mma.sync.aligned.m16n8k16.row.col.f32.f16.f16.f32 "
                 "{%0,%1,%2,%3},{%4,%5,%6,%7},{%8,%9},{%0,%1,%2,%3};"
                 : "+f"(c0), "+f"(c1), "+f"(c2), "+f"(c3)
                 : "r"(a0), "r"(a1), "r"(a2), "r"(a3), "r"(b0), "r"(b1));
}
#define H2C(q, k) (*((const __half2*)&(q) + (k)))
#define ACCQ(q) { \
    float2 f0 = __half22float2(H2C(q,0)); \
    float2 f1 = __half22float2(H2C(q,1)); \
    float2 f2 = __half22float2(H2C(q,2)); \
    float2 f3 = __half22float2(H2C(q,3)); \
    a0+=f0.x; a1+=f0.y; a2+=f1.x; a3+=f1.y; \
    a4+=f2.x; a5+=f2.y; a6+=f3.x; a7+=f3.y; }
#define ACC4(q0, q1, q2, q3) { \
    __half2 s0 = __hadd2(__hadd2(H2C(q0,0), H2C(q1,0)), __hadd2(H2C(q2,0), H2C(q3,0))); \
    __half2 s1 = __hadd2(__hadd2(H2C(q0,1), H2C(q1,1)), __hadd2(H2C(q2,1), H2C(q3,1))); \
    __half2 s2 = __hadd2(__hadd2(H2C(q0,2), H2C(q1,2)), __hadd2(H2C(q2,2), H2C(q3,2))); \
    __half2 s3 = __hadd2(__hadd2(H2C(q0,3), H2C(q1,3)), __hadd2(H2C(q2,3), H2C(q3,3))); \
    float2 f0 = __half22float2(s0); float2 f1 = __half22float2(s1); \
    float2 f2 = __half22float2(s2); float2 f3 = __half22float2(s3); \
    a0+=f0.x; a1+=f0.y; a2+=f1.x; a3+=f1.y; \
    a4+=f2.x; a5+=f2.y; a6+=f3.x; a7+=f3.y; }

// ---------------- setup kernels ----------------

__global__ void k_zero_main() {
    int i = blockIdx.x * blockDim.x + threadIdx.x;
    int stride = gridDim.x * blockDim.x;
    for (int j = i; j < Nn; j += stride) g_deg[j] = 0;
    for (int j = i; j < NT; j += stride) g_tilest[j] = 0u;
    if (i == 0) g_ticket = 0;
}

__global__ void k_zero_aux() {
    int i = blockIdx.x * blockDim.x + threadIdx.x;
    int stride = gridDim.x * blockDim.x;
    for (int j = i; j < Bb * HID; j += stride) g_hg[j] = 0.f;
    if (i < Bb) { g_gfirst[i] = 0; g_glast[i] = 0; }
}

// degree histogram, 4 edges/thread (atomic return = edge rank, MLP=4)
__global__ void k_deg(const int* __restrict__ dst) {
    int i = blockIdx.x * blockDim.x + threadIdx.x;
    int e = i * 4;
    if (e + 3 < Ee) {
        int4 d = *(const int4*)(dst + e);
        int r0 = atomicAdd(&g_deg[d.x], 1);
        int r1 = atomicAdd(&g_deg[d.y], 1);
        int r2 = atomicAdd(&g_deg[d.z], 1);
        int r3 = atomicAdd(&g_deg[d.w], 1);
        *(int4*)(g_rank + e) = make_int4(r0, r1, r2, r3);
    } else {
        for (; e < Ee; e++) g_rank[e] = atomicAdd(&g_deg[dst[e]], 1);
    }
}

// embedding gather (fp16) + sorted-segment boundaries (stream 2)
__global__ void k_gather(const int* __restrict__ node_ids,
                         const int* __restrict__ graph_ids,
                         const float4* __restrict__ emb) {
    int i = blockIdx.x * blockDim.x + threadIdx.x;
    if (i < Nn * 4) {
        int n = i >> 2, c = i & 3;
        float4 v0 = emb[node_ids[n] * 8 + c * 2 + 0];
        float4 v1 = emb[node_ids[n] * 8 + c * 2 + 1];
        uint4 o;
        o.x = ph2(v0.x, v0.y); o.y = ph2(v0.z, v0.w);
        o.z = ph2(v1.x, v1.y); o.w = ph2(v1.z, v1.w);
        g_h0h[n * 4 + c] = o;
    }
    if (i < Nn) {
        int g = graph_ids[i];
        if (i == 0 || graph_ids[i-1] != g)      g_gfirst[g] = i;
        if (i == Nn-1 || graph_ids[i+1] != g)   g_glast[g]  = i + 1;
    }
}

__global__ void __launch_bounds__(256) k_scan() {
    __shared__ int s_ticket, s_run;
    __shared__ int ssum[256];
    int tid = threadIdx.x;
    if (tid == 0) s_ticket = atomicAdd(&g_ticket, 1);
    __syncthreads();
    int t = s_ticket;
    int base = t * TILE + tid * 4;
    int d[4]; int s = 0;
    #pragma unroll
    for (int it = 0; it < 4; it++) {
        int idx = base + it;
        d[it] = (idx < Nn) ? g_deg[idx] : 0;
        s += d[it];
    }
    ssum[tid] = s; __syncthreads();
    #pragma unroll
    for (int off = 1; off < 256; off <<= 1) {
        int x = (tid >= off) ? ssum[tid - off] : 0;
        __syncthreads();
        ssum[tid] += x;
        __syncthreads();
    }
    int texcl = ssum[tid] - s;
    int total = ssum[255];
    if (tid == 0) {
        if (t == 0) {
            g_tilest[0] = (2u << 30) | (unsigned)total;
            s_run = 0;
        } else {
            g_tilest[t] = (1u << 30) | (unsigned)total;
            int run = 0, p = t - 1;
            while (true) {
                unsigned w = g_tilest[p];
                unsigned f = w >> 30;
                if (f == 2u) { run += (int)(w & 0x3FFFFFFFu); break; }
                if (f == 1u) { run += (int)(w & 0x3FFFFFFFu); p--; }
            }
            g_tilest[t] = (2u << 30) | (unsigned)(run + total);
            s_run = run;
        }
    }
    __syncthreads();
    int ex = s_run + texcl;
    #pragma unroll
    for (int it = 0; it < 4; it++) {
        int idx = base + it;
        if (idx < Nn) {
            g_rowptr[idx] = ex;
            int dd = d[it];
            g_dinv[idx] = (dd > 0) ? 1.0f / (float)dd : 0.0f;
            ex += dd;
        }
    }
}

// CSR fill, 4 edges/thread, atomic-free
__global__ void k_fill(const int* __restrict__ src, const int* __restrict__ dst) {
    int i = blockIdx.x * blockDim.x + threadIdx.x;
    int e = i * 4;
    if (e + 3 < Ee) {
        int4 d = *(const int4*)(dst + e);
        int4 s = *(const int4*)(src + e);
        int4 r = *(const int4*)(g_rank + e);
        g_csr[g_rowptr[d.x] + r.x] = s.x;
        g_csr[g_rowptr[d.y] + r.y] = s.y;
        g_csr[g_rowptr[d.z] + r.z] = s.z;
        g_csr[g_rowptr[d.w] + r.w] = s.w;
    } else {
        for (; e < Ee; e++) g_csr[g_rowptr[dst[e]] + g_rank[e]] = src[e];
    }
}

// ---------------- aggregation: pipelined index prefetch, pairwise fp16 ------------

__global__ void k_agg1() {
    int t = blockIdx.x * blockDim.x + threadIdx.x;
    if (t >= Nn * 4) return;
    int n = t >> 2, c = t & 3;
    int beg = g_rowptr[n], cnt = g_deg[n];
    float a0=0.f,a1=0.f,a2=0.f,a3=0.f,a4=0.f,a5=0.f,a6=0.f,a7=0.f;
    int i = 0;
    int idxA[8];
    if (i + 7 < cnt) {
        #pragma unroll
        for (int j = 0; j < 8; j++) idxA[j] = __ldg(&g_csr[beg + i + j]);
    }
    while (i + 7 < cnt) {
        int inext = i + 8;
        int idxB[8];
        if (inext + 7 < cnt) {
            #pragma unroll
            for (int j = 0; j < 8; j++) idxB[j] = __ldg(&g_csr[beg + inext + j]);
        }
        uint4 q0 = g_h0h[idxA[0]*4+c], q1 = g_h0h[idxA[1]*4+c];
        uint4 q2 = g_h0h[idxA[2]*4+c], q3 = g_h0h[idxA[3]*4+c];
        uint4 q4 = g_h0h[idxA[4]*4+c], q5 = g_h0h[idxA[5]*4+c];
        uint4 q6 = g_h0h[idxA[6]*4+c], q7 = g_h0h[idxA[7]*4+c];
        ACC4(q0, q1, q2, q3)
        ACC4(q4, q5, q6, q7)
        #pragma unroll
        for (int j = 0; j < 8; j++) idxA[j] = idxB[j];
        i = inext;
    }
    for (; i + 3 < cnt; i += 4) {
        int s0 = __ldg(&g_csr[beg+i+0]), s1 = __ldg(&g_csr[beg+i+1]);
        int s2 = __ldg(&g_csr[beg+i+2]), s3 = __ldg(&g_csr[beg+i+3]);
        uint4 q0 = g_h0h[s0*4+c], q1 = g_h0h[s1*4+c];
        uint4 q2 = g_h0h[s2*4+c], q3 = g_h0h[s3*4+c];
        ACC4(q0, q1, q2, q3)
    }
    for (; i < cnt; i++) {
        int s = __ldg(&g_csr[beg+i]);
        uint4 q = g_h0h[s*4+c];
        ACCQ(q)
    }
    float dinv = g_dinv[n];
    uint4 o;
    o.x = ph2(a0*dinv, a1*dinv); o.y = ph2(a2*dinv, a3*dinv);
    o.z = ph2(a4*dinv, a5*dinv); o.w = ph2(a6*dinv, a7*dinv);
    g_ag1h[n*4 + c] = o;
}

__global__ void k_agg2() {
    int t = blockIdx.x * blockDim.x + threadIdx.x;
    if (t >= Nn * 8) return;
    int n = t >> 3, c = t & 7;
    int beg = g_rowptr[n], cnt = g_deg[n];
    float a0=0.f,a1=0.f,a2=0.f,a3=0.f,a4=0.f,a5=0.f,a6=0.f,a7=0.f;
    int i = 0;
    int idxA[8];
    if (i + 7 < cnt) {
        #pragma unroll
        for (int j = 0; j < 8; j++) idxA[j] = __ldg(&g_csr[beg + i + j]);
    }
    while (i + 7 < cnt) {
        int inext = i + 8;
        int idxB[8];
        if (inext + 7 < cnt) {
            #pragma unroll
            for (int j = 0; j < 8; j++) idxB[j] = __ldg(&g_csr[beg + inext + j]);
        }
        uint4 q0 = g_h1h[idxA[0]*8+c], q1 = g_h1h[idxA[1]*8+c];
        uint4 q2 = g_h1h[idxA[2]*8+c], q3 = g_h1h[idxA[3]*8+c];
        uint4 q4 = g_h1h[idxA[4]*8+c], q5 = g_h1h[idxA[5]*8+c];
        uint4 q6 = g_h1h[idxA[6]*8+c], q7 = g_h1h[idxA[7]*8+c];
        ACC4(q0, q1, q2, q3)
        ACC4(q4, q5, q6, q7)
        #pragma unroll
        for (int j = 0; j < 8; j++) idxA[j] = idxB[j];
        i = inext;
    }
    for (; i + 3 < cnt; i += 4) {
        int s0 = __ldg(&g_csr[beg+i+0]), s1 = __ldg(&g_csr[beg+i+1]);
        int s2 = __ldg(&g_csr[beg+i+2]), s3 = __ldg(&g_csr[beg+i+3]);
        uint4 q0 = g_h1h[s0*8+c], q1 = g_h1h[s1*8+c];
        uint4 q2 = g_h1h[s2*8+c], q3 = g_h1h[s3*8+c];
        ACC4(q0, q1, q2, q3)
    }
    for (; i < cnt; i++) {
        int s = __ldg(&g_csr[beg+i]);
        uint4 q = g_h1h[s*8+c];
        ACCQ(q)
    }
    float dinv = g_dinv[n];
    uint4 o;
    o.x = ph2(a0*dinv, a1*dinv); o.y = ph2(a2*dinv, a3*dinv);
    o.z = ph2(a4*dinv, a5*dinv); o.w = ph2(a6*dinv, a7*dinv);
    g_ag2h[n*8 + c] = o;
}

// ---------------- tensor-core dense updates (mma.sync m16n8k16) ----------------

__global__ void __launch_bounds__(256)
k_update1_mma(const float* __restrict__ Wse, const float* __restrict__ Wne,
              const float* __restrict__ b) {
    const int K = 2 * EMB;
    const int WS = 72;
    __shared__ __half sWt[HID * WS];
    __shared__ float sb[HID];
    int tid = threadIdx.x;
    for (int i = tid; i < HID * K; i += 256) {
        int n = i >> 6, k = i & 63;
        float w = (k < EMB) ? Wse[k * HID + n] : Wne[(k - EMB) * HID + n];
        sWt[n * WS + k] = __float2half(w);
    }
    if (tid < HID) sb[tid] = b[tid];
    __syncthreads();

    int warp = tid >> 5, lane = tid & 31;
    int gid = lane >> 2, c = lane & 3;
    const __half* fh = (const __half*)g_h0h;
    const __half* fa = (const __half*)g_ag1h;
    __half* out = (__half*)g_h1h;

    #pragma unroll 1
    for (int mt = 0; mt < 2; mt++) {
        int m = blockIdx.x * 256 + warp * 32 + mt * 16;
        if (m >= Nn) break;
        int r0 = m + gid, r1 = r0 + 8;

        float acc[8][4];
        #pragma unroll
        for (int nt = 0; nt < 8; nt++) {
            float b0 = sb[nt*8 + 2*c], b1 = sb[nt*8 + 2*c + 1];
            acc[nt][0] = b0; acc[nt][1] = b1; acc[nt][2] = b0; acc[nt][3] = b1;
        }

        #pragma unroll
        for (int kk = 0; kk < 4; kk++) {
            int k0 = kk * 16;
            const __half* src = (kk < 2) ? fh : fa;
            int koff = (kk < 2) ? k0 : k0 - EMB;
            u32 a0 = *(const u32*)(src + r0*EMB + koff + 2*c);
            u32 a1 = *(const u32*)(src + r1*EMB + koff + 2*c);
            u32 a2 = *(const u32*)(src + r0*EMB + koff + 8 + 2*c);
            u32 a3 = *(const u32*)(src + r1*EMB + koff + 8 + 2*c);
            #pragma unroll
            for (int nt = 0; nt < 8; nt++) {
                int n = nt*8 + gid;
                u32 b0 = *(const u32*)&sWt[n * WS + k0 + 2*c];
                u32 b1 = *(const u32*)&sWt[n * WS + k0 + 8 + 2*c];
                mma16816(acc[nt][0], acc[nt][1], acc[nt][2], acc[nt][3],
                         a0, a1, a2, a3, b0, b1);
            }
        }

        #pragma unroll
        for (int nt = 0; nt < 8; nt++) {
            int col = nt*8 + 2*c;
            *(u32*)(out + r0*HID + col) = ph2(fmaxf(acc[nt][0],0.f), fmaxf(acc[nt][1],0.f));
            *(u32*)(out + r1*HID + col) = ph2(fmaxf(acc[nt][2],0.f), fmaxf(acc[nt][3],0.f));
        }
    }
}

__global__ void __launch_bounds__(256)
k_update2_mma(const float* __restrict__ Wse, const float* __restrict__ Wne,
              const float* __restrict__ b, const int* __restrict__ graph_ids) {
    const int K = 2 * HID;
    const int WS = 136;
    __shared__ __half sWt[HID * WS];
    __shared__ float sb[HID];
    int tid = threadIdx.x;
    for (int i = tid; i < HID * K; i += 256) {
        int n = i >> 7, k = i & 127;
        float w = (k < HID) ? Wse[k * HID + n] : Wne[(k - HID) * HID + n];
        sWt[n * WS + k] = __float2half(w);
    }
    if (tid < HID) sb[tid] = b[tid];
    __syncthreads();

    int warp = tid >> 5, lane = tid & 31;
    int gid = lane >> 2, c = lane & 3;
    const __half* fh = (const __half*)g_h1h;
    const __half* fa = (const __half*)g_ag2h;

    #pragma unroll 1
    for (int mt = 0; mt < 2; mt++) {
        int m = blockIdx.x * 256 + warp * 32 + mt * 16;
        if (m >= Nn) break;
        int r0 = m + gid, r1 = r0 + 8;
        int g0 = graph_ids[r0], g1 = graph_ids[r1];

        float acc[8][4];
        #pragma unroll
        for (int nt = 0; nt < 8; nt++) {
            float b0 = sb[nt*8 + 2*c], b1 = sb[nt*8 + 2*c + 1];
            acc[nt][0] = b0; acc[nt][1] = b1; acc[nt][2] = b0; acc[nt][3] = b1;
        }

        #pragma unroll
        for (int kk = 0; kk < 8; kk++) {
            int k0 = kk * 16;
            const __half* src = (kk < 4) ? fh : fa;
            int koff = (kk < 4) ? k0 : k0 - HID;
            u32 a0 = *(const u32*)(src + r0*HID + koff + 2*c);
            u32 a1 = *(const u32*)(src + r1*HID + koff + 2*c);
            u32 a2 = *(const u32*)(src + r0*HID + koff + 8 + 2*c);
            u32 a3 = *(const u32*)(src + r1*HID + koff + 8 + 2*c);
            #pragma unroll
            for (int nt = 0; nt < 8; nt++) {
                int n = nt*8 + gid;
                u32 b0 = *(const u32*)&sWt[n * WS + k0 + 2*c];
                u32 b1 = *(const u32*)&sWt[n * WS + k0 + 8 + 2*c];
                mma16816(acc[nt][0], acc[nt][1], acc[nt][2], acc[nt][3],
                         a0, a1, a2, a3, b0, b1);
            }
        }

        #pragma unroll
        for (int nt = 0; nt < 8; nt++) {
            int col = nt*8 + 2*c;
            red2(&g_hg[g0*HID + col], fmaxf(acc[nt][0],0.f), fmaxf(acc[nt][1],0.f));
            red2(&g_hg[g1*HID + col], fmaxf(acc[nt][2],0.f), fmaxf(acc[nt][3],0.f));
        }
    }
}

// scorer
__global__ void k_final(const float* __restrict__ Ws1, const float* __restrict__ bs1,
                        const float* __restrict__ Ws2, const float* __restrict__ bs2,
                        float* __restrict__ out) {
    __shared__ float sW[HID * HID];
    int tid = threadIdx.x;
    for (int i = tid; i < HID * HID; i += 64) sW[i] = Ws1[i];
    __syncthreads();

    int g = blockIdx.x * 64 + tid;
    if (g >= Bb) return;

    float cv = (float)(g_glast[g] - g_gfirst[g]);
    float inv = 1.0f / fmaxf(cv, 1.0f);
    float hv[HID];
    #pragma unroll
    for (int k = 0; k < HID; k++) hv[k] = g_hg[g * HID + k] * inv;

    float s = bs2[0];
    #pragma unroll 1
    for (int j = 0; j < HID; j++) {
        float t = bs1[j];
        #pragma unroll
        for (int k = 0; k < HID; k++) t += hv[k] * sW[k * HID + j];
        s += fmaxf(t, 0.f) * Ws2[j];
    }
    out[g] = s;
}

// ---------------- launcher ----------------
extern "C" void kernel_launch(void* const* d_in, const int* in_sizes, int n_in,
                              void* d_out, int out_size) {
    const int*    node_ids  = (const int*)   d_in[0];
    const int*    src       = (const int*)   d_in[1];
    const int*    dst       = (const int*)   d_in[2];
    const int*    graph_ids = (const int*)   d_in[3];
    const float4* emb       = (const float4*)d_in[4];
    const float*  W_self1   = (const float*) d_in[5];
    const float*  W_neigh1  = (const float*) d_in[6];
    const float*  b1        = (const float*) d_in[7];
    const float*  W_self2   = (const float*) d_in[8];
    const float*  W_neigh2  = (const float*) d_in[9];
    const float*  b2        = (const float*) d_in[10];
    const float*  Ws1       = (const float*) d_in[11];
    const float*  bs1       = (const float*) d_in[12];
    const float*  Ws2       = (const float*) d_in[13];
    const float*  bs2       = (const float*) d_in[14];
    float* out = (float*)d_out;

    static cudaStream_t s2 = nullptr;
    static cudaEvent_t ev_fork = nullptr, ev_join = nullptr;
    if (s2 == nullptr) {
        cudaStreamCreateWithFlags(&s2, cudaStreamNonBlocking);
        cudaEventCreateWithFlags(&ev_fork, cudaEventDisableTiming);
        cudaEventCreateWithFlags(&ev_join, cudaEventDisableTiming);
    }

    // fork: gather + aux zero on side stream
    cudaEventRecord(ev_fork, 0);
    cudaStreamWaitEvent(s2, ev_fork, 0);
    k_zero_aux<<<64, 256, 0, s2>>>();
    k_gather  <<<(Nn * 4 + 255) / 256, 256, 0, s2>>>(node_ids, graph_ids, emb);
    cudaEventRecord(ev_join, s2);

    // main chain
    k_zero_main<<<256, 256>>>();
    k_deg      <<<(Ee/4 + 255) / 256, 256>>>(dst);
    k_scan     <<<NT, 256>>>();
    k_fill     <<<(Ee/4 + 255) / 256, 256>>>(src, dst);

    cudaStreamWaitEvent(0, ev_join, 0);
    k_agg1       <<<(Nn * 4 + 255) / 256, 256>>>();
    k_update1_mma<<<NUB, 256>>>(W_self1, W_neigh1, b1);
    k_agg2       <<<(Nn * 8 + 255) / 256, 256>>>();
    k_update2_mma<<<NUB, 256>>>(W_self2, W_neigh2, b2, graph_ids);
    k_final      <<<(Bb + 63) / 64, 64>>>(Ws1, bs1, Ws2, bs2, out);
}

// round 17
// speedup vs baseline: 1.0497x; 1.0497x over previous
#include <cuda_runtime.h>
#include <cuda_fp16.h>

typedef unsigned long long u64;
typedef unsigned int u32;

#define Nn   200000
#define Ee   3200000
#define Bb   512
#define EMB  32
#define HID  64
#define TILE 1024
#define NT   ((Nn + TILE - 1) / TILE)   // 196 scan tiles
#define NUB  ((Nn + 255) / 256)         // update blocks

// ---------------- scratch (device globals; zero at module load) ----------------
// Invariants maintained across calls WITHOUT a zero kernel:
//  - g_deg returns to all-zero (k_scan writes 0 back after reading)
//  - g_tilest entries are epoch-tagged (monotonic g_ticket), stale = not-ready
//  - g_hg zeroed inside k_deg (before any update2 writes this call)
__device__ uint4 g_h0h [Nn * 4];          // 12.8 MB fp16 h0 (32 ch)
__device__ uint4 g_ag1h[Nn * 4];          // 12.8 MB fp16 agg1
__device__ uint4 g_h1h [Nn * 8];          // 25.6 MB fp16 h1 (64 ch)
__device__ uint4 g_ag2h[Nn * 8];          // 25.6 MB fp16 agg2
__device__ int   g_csr [Ee];
__device__ int   g_rank[Ee];
__device__ int   g_rowptr[Nn + 1];
__device__ int   g_deg [Nn];
__device__ float g_dinv[Nn];
__device__ float g_hg  [Bb * HID];
__device__ int   g_gfirst[Bb];
__device__ int   g_glast [Bb];
__device__ volatile u64 g_tilest[NT];
__device__ int   g_ticket;                // monotonic across calls

// ---------------- helpers ----------------
__device__ __forceinline__ void red2(float* p, float x, float y) {
    asm volatile("red.global.add.v2.f32 [%0], {%1,%2};"
                 :: "l"(p), "f"(x), "f"(y) : "memory");
}
__device__ __forceinline__ unsigned ph2(float a, float b) {
    __half2 h = __floats2half2_rn(a, b); return *(unsigned*)&h;
}
__device__ __forceinline__ void mma16816(float& c0, float& c1, float& c2, float& c3,
                                         u32 a0, u32 a1, u32 a2, u32 a3,
                                         u32 b0, u32 b1) {
    asm volatile("mma.sync.aligned.m16n8k16.row.col.f32.f16.f16.f32 "
                 "{%0,%1,%2,%3},{%4,%5,%6,%7},{%8,%9},{%0,%1,%2,%3};"
                 : "+f"(c0), "+f"(c1), "+f"(c2), "+f"(c3)
                 : "r"(a0), "r"(a1), "r"(a2), "r"(a3), "r"(b0), "r"(b1));
}
#define H2C(q, k) (*((const __half2*)&(q) + (k)))
#define ACCQ(q) { \
    float2 f0 = __half22float2(H2C(q,0)); \
    float2 f1 = __half22float2(H2C(q,1)); \
    float2 f2 = __half22float2(H2C(q,2)); \
    float2 f3 = __half22float2(H2C(q,3)); \
    a0+=f0.x; a1+=f0.y; a2+=f1.x; a3+=f1.y; \
    a4+=f2.x; a5+=f2.y; a6+=f3.x; a7+=f3.y; }
#define ACC4(q0, q1, q2, q3) { \
    __half2 s0 = __hadd2(__hadd2(H2C(q0,0), H2C(q1,0)), __hadd2(H2C(q2,0), H2C(q3,0))); \
    __half2 s1 = __hadd2(__hadd2(H2C(q0,1), H2C(q1,1)), __hadd2(H2C(q2,1), H2C(q3,1))); \
    __half2 s2 = __hadd2(__hadd2(H2C(q0,2), H2C(q1,2)), __hadd2(H2C(q2,2), H2C(q3,2))); \
    __half2 s3 = __hadd2(__hadd2(H2C(q0,3), H2C(q1,3)), __hadd2(H2C(q2,3), H2C(q3,3))); \
    float2 f0 = __half22float2(s0); float2 f1 = __half22float2(s1); \
    float2 f2 = __half22float2(s2); float2 f3 = __half22float2(s3); \
    a0+=f0.x; a1+=f0.y; a2+=f1.x; a3+=f1.y; \
    a4+=f2.x; a5+=f2.y; a6+=f3.x; a7+=f3.y; }

// ---------------- setup kernels ----------------

// degree histogram (atomic return = edge rank) + segment boundaries + hg zero ride-along
__global__ void k_deg(const int* __restrict__ dst,
                      const int* __restrict__ graph_ids) {
    int i = blockIdx.x * blockDim.x + threadIdx.x;
    if (i < Ee) g_rank[i] = atomicAdd(&g_deg[dst[i]], 1);
    if (i < Nn) {
        int g = graph_ids[i];
        if (i == 0 || graph_ids[i-1] != g)      g_gfirst[g] = i;
        if (i == Nn-1 || graph_ids[i+1] != g)   g_glast[g]  = i + 1;
    }
    if (i < Bb * HID) g_hg[i] = 0.f;
}

// decoupled-lookback exclusive scan; epoch-tagged status; deg self-reset
__global__ void __launch_bounds__(256) k_scan() {
    __shared__ int s_ticket, s_run;
    __shared__ int ssum[256];
    int tid = threadIdx.x;
    if (tid == 0) s_ticket = atomicAdd(&g_ticket, 1);
    __syncthreads();
    int tk = s_ticket;
    int t  = tk % NT;
    u32 ep = (u32)(tk / NT);

    int base = t * TILE + tid * 4;
    int d[4]; int s = 0;
    #pragma unroll
    for (int it = 0; it < 4; it++) {
        int idx = base + it;
        if (idx < Nn) {
            d[it] = g_deg[idx];
            g_deg[idx] = 0;            // restore zero invariant for next call
        } else d[it] = 0;
        s += d[it];
    }
    ssum[tid] = s; __syncthreads();
    #pragma unroll
    for (int off = 1; off < 256; off <<= 1) {
        int x = (tid >= off) ? ssum[tid - off] : 0;
        __syncthreads();
        ssum[tid] += x;
        __syncthreads();
    }
    int texcl = ssum[tid] - s;
    int total = ssum[255];
    if (tid == 0) {
        if (t == 0) {
            g_tilest[0] = ((u64)ep << 32) | (2u << 30) | (u32)total;
            s_run = 0;
        } else {
            g_tilest[t] = ((u64)ep << 32) | (1u << 30) | (u32)total;
            int run = 0, p = t - 1;
            while (true) {
                u64 w = g_tilest[p];
                if ((u32)(w >> 32) != ep) continue;   // stale/not written yet
                u32 f = ((u32)w) >> 30;
                u32 v = (u32)w & 0x3FFFFFFFu;
                if (f == 2u) { run += (int)v; break; }
                if (f == 1u) { run += (int)v; p--; }
            }
            g_tilest[t] = ((u64)ep << 32) | (2u << 30) | (u32)(run + total);
            s_run = run;
        }
    }
    __syncthreads();
    int ex = s_run + texcl;
    #pragma unroll
    for (int it = 0; it < 4; it++) {
        int idx = base + it;
        if (idx < Nn) {
            g_rowptr[idx] = ex;
            int dd = d[it];
            g_dinv[idx] = (dd > 0) ? 1.0f / (float)dd : 0.0f;
            ex += dd;
            if (idx == Nn - 1) g_rowptr[Nn] = ex;
        }
    }
}

// CSR fill (atomic-free) + embedding gather ride-along
__global__ void k_fill_gather(const int* __restrict__ src, const int* __restrict__ dst,
                              const int* __restrict__ node_ids,
                              const float4* __restrict__ emb) {
    int i = blockIdx.x * blockDim.x + threadIdx.x;
    if (i < Ee) {
        int d = dst[i];
        g_csr[g_rowptr[d] + g_rank[i]] = src[i];
    }
    if (i < Nn * 4) {
        int n = i >> 2, c = i & 3;
        float4 v0 = emb[node_ids[n] * 8 + c * 2 + 0];
        float4 v1 = emb[node_ids[n] * 8 + c * 2 + 1];
        uint4 o;
        o.x = ph2(v0.x, v0.y); o.y = ph2(v0.z, v0.w);
        o.z = ph2(v1.x, v1.y); o.w = ph2(v1.z, v1.w);
        g_h0h[n * 4 + c] = o;
    }
}

// ---------------- aggregation (pairwise fp16, fp32 outer) ----------------

__global__ void k_agg1() {
    int t = blockIdx.x * blockDim.x + threadIdx.x;
    if (t >= Nn * 4) return;
    int n = t >> 2, c = t & 3;
    int beg = g_rowptr[n], cnt = g_rowptr[n + 1] - beg;
    float a0=0.f,a1=0.f,a2=0.f,a3=0.f,a4=0.f,a5=0.f,a6=0.f,a7=0.f;
    int i = 0;
    for (; i + 7 < cnt; i += 8) {
        int s0 = __ldg(&g_csr[beg+i+0]), s1 = __ldg(&g_csr[beg+i+1]);
        int s2 = __ldg(&g_csr[beg+i+2]), s3 = __ldg(&g_csr[beg+i+3]);
        int s4 = __ldg(&g_csr[beg+i+4]), s5 = __ldg(&g_csr[beg+i+5]);
        int s6 = __ldg(&g_csr[beg+i+6]), s7 = __ldg(&g_csr[beg+i+7]);
        uint4 q0 = g_h0h[s0*4+c], q1 = g_h0h[s1*4+c];
        uint4 q2 = g_h0h[s2*4+c], q3 = g_h0h[s3*4+c];
        uint4 q4 = g_h0h[s4*4+c], q5 = g_h0h[s5*4+c];
        uint4 q6 = g_h0h[s6*4+c], q7 = g_h0h[s7*4+c];
        ACC4(q0, q1, q2, q3)
        ACC4(q4, q5, q6, q7)
    }
    for (; i + 3 < cnt; i += 4) {
        int s0 = __ldg(&g_csr[beg+i+0]), s1 = __ldg(&g_csr[beg+i+1]);
        int s2 = __ldg(&g_csr[beg+i+2]), s3 = __ldg(&g_csr[beg+i+3]);
        uint4 q0 = g_h0h[s0*4+c], q1 = g_h0h[s1*4+c];
        uint4 q2 = g_h0h[s2*4+c], q3 = g_h0h[s3*4+c];
        ACC4(q0, q1, q2, q3)
    }
    for (; i < cnt; i++) {
        int s = __ldg(&g_csr[beg+i]);
        uint4 q = g_h0h[s*4+c];
        ACCQ(q)
    }
    float dinv = g_dinv[n];
    uint4 o;
    o.x = ph2(a0*dinv, a1*dinv); o.y = ph2(a2*dinv, a3*dinv);
    o.z = ph2(a4*dinv, a5*dinv); o.w = ph2(a6*dinv, a7*dinv);
    g_ag1h[n*4 + c] = o;
}

__global__ void k_agg2() {
    int t = blockIdx.x * blockDim.x + threadIdx.x;
    if (t >= Nn * 8) return;
    int n = t >> 3, c = t & 7;
    int beg = g_rowptr[n], cnt = g_rowptr[n + 1] - beg;
    float a0=0.f,a1=0.f,a2=0.f,a3=0.f,a4=0.f,a5=0.f,a6=0.f,a7=0.f;
    int i = 0;
    for (; i + 7 < cnt; i += 8) {
        int s0 = __ldg(&g_csr[beg+i+0]), s1 = __ldg(&g_csr[beg+i+1]);
        int s2 = __ldg(&g_csr[beg+i+2]), s3 = __ldg(&g_csr[beg+i+3]);
        int s4 = __ldg(&g_csr[beg+i+4]), s5 = __ldg(&g_csr[beg+i+5]);
        int s6 = __ldg(&g_csr[beg+i+6]), s7 = __ldg(&g_csr[beg+i+7]);
        uint4 q0 = g_h1h[s0*8+c], q1 = g_h1h[s1*8+c];
        uint4 q2 = g_h1h[s2*8+c], q3 = g_h1h[s3*8+c];
        uint4 q4 = g_h1h[s4*8+c], q5 = g_h1h[s5*8+c];
        uint4 q6 = g_h1h[s6*8+c], q7 = g_h1h[s7*8+c];
        ACC4(q0, q1, q2, q3)
        ACC4(q4, q5, q6, q7)
    }
    for (; i + 3 < cnt; i += 4) {
        int s0 = __ldg(&g_csr[beg+i+0]), s1 = __ldg(&g_csr[beg+i+1]);
        int s2 = __ldg(&g_csr[beg+i+2]), s3 = __ldg(&g_csr[beg+i+3]);
        uint4 q0 = g_h1h[s0*8+c], q1 = g_h1h[s1*8+c];
        uint4 q2 = g_h1h[s2*8+c], q3 = g_h1h[s3*8+c];
        ACC4(q0, q1, q2, q3)
    }
    for (; i < cnt; i++) {
        int s = __ldg(&g_csr[beg+i]);
        uint4 q = g_h1h[s*8+c];
        ACCQ(q)
    }
    float dinv = g_dinv[n];
    uint4 o;
    o.x = ph2(a0*dinv, a1*dinv); o.y = ph2(a2*dinv, a3*dinv);
    o.z = ph2(a4*dinv, a5*dinv); o.w = ph2(a6*dinv, a7*dinv);
    g_ag2h[n*8 + c] = o;
}

// ---------------- tensor-core dense updates (mma.sync m16n8k16) ----------------

__global__ void __launch_bounds__(256)
k_update1_mma(const float* __restrict__ Wse, const float* __restrict__ Wne,
              const float* __restrict__ b) {
    const int K = 2 * EMB;
    const int WS = 72;
    __shared__ __half sWt[HID * WS];
    __shared__ float sb[HID];
    int tid = threadIdx.x;
    for (int i = tid; i < HID * K; i += 256) {
        int n = i >> 6, k = i & 63;
        float w = (k < EMB) ? Wse[k * HID + n] : Wne[(k - EMB) * HID + n];
        sWt[n * WS + k] = __float2half(w);
    }
    if (tid < HID) sb[tid] = b[tid];
    __syncthreads();

    int warp = tid >> 5, lane = tid & 31;
    int gid = lane >> 2, c = lane & 3;
    const __half* fh = (const __half*)g_h0h;
    const __half* fa = (const __half*)g_ag1h;
    __half* out = (__half*)g_h1h;

    #pragma unroll 1
    for (int mt = 0; mt < 2; mt++) {
        int m = blockIdx.x * 256 + warp * 32 + mt * 16;
        if (m >= Nn) break;
        int r0 = m + gid, r1 = r0 + 8;

        float acc[8][4];
        #pragma unroll
        for (int nt = 0; nt < 8; nt++) {
            float b0 = sb[nt*8 + 2*c], b1 = sb[nt*8 + 2*c + 1];
            acc[nt][0] = b0; acc[nt][1] = b1; acc[nt][2] = b0; acc[nt][3] = b1;
        }

        #pragma unroll
        for (int kk = 0; kk < 4; kk++) {
            int k0 = kk * 16;
            const __half* src = (kk < 2) ? fh : fa;
            int koff = (kk < 2) ? k0 : k0 - EMB;
            u32 a0 = *(const u32*)(src + r0*EMB + koff + 2*c);
            u32 a1 = *(const u32*)(src + r1*EMB + koff + 2*c);
            u32 a2 = *(const u32*)(src + r0*EMB + koff + 8 + 2*c);
            u32 a3 = *(const u32*)(src + r1*EMB + koff + 8 + 2*c);
            #pragma unroll
            for (int nt = 0; nt < 8; nt++) {
                int n = nt*8 + gid;
                u32 b0 = *(const u32*)&sWt[n * WS + k0 + 2*c];
                u32 b1 = *(const u32*)&sWt[n * WS + k0 + 8 + 2*c];
                mma16816(acc[nt][0], acc[nt][1], acc[nt][2], acc[nt][3],
                         a0, a1, a2, a3, b0, b1);
            }
        }

        #pragma unroll
        for (int nt = 0; nt < 8; nt++) {
            int col = nt*8 + 2*c;
            *(u32*)(out + r0*HID + col) = ph2(fmaxf(acc[nt][0],0.f), fmaxf(acc[nt][1],0.f));
            *(u32*)(out + r1*HID + col) = ph2(fmaxf(acc[nt][2],0.f), fmaxf(acc[nt][3],0.f));
        }
    }
}

__global__ void __launch_bounds__(256)
k_update2_mma(const float* __restrict__ Wse, const float* __restrict__ Wne,
              const float* __restrict__ b, const int* __restrict__ graph_ids) {
    const int K = 2 * HID;
    const int WS = 136;
    __shared__ __half sWt[HID * WS];
    __shared__ float sb[HID];
    int tid = threadIdx.x;
    for (int i = tid; i < HID * K; i += 256) {
        int n = i >> 7, k = i & 127;
        float w = (k < HID) ? Wse[k * HID + n] : Wne[(k - HID) * HID + n];
        sWt[n * WS + k] = __float2half(w);
    }
    if (tid < HID) sb[tid] = b[tid];
    __syncthreads();

    int warp = tid >> 5, lane = tid & 31;
    int gid = lane >> 2, c = lane & 3;
    const __half* fh = (const __half*)g_h1h;
    const __half* fa = (const __half*)g_ag2h;

    #pragma unroll 1
    for (int mt = 0; mt < 2; mt++) {
        int m = blockIdx.x * 256 + warp * 32 + mt * 16;
        if (m >= Nn) break;
        int r0 = m + gid, r1 = r0 + 8;
        int g0 = graph_ids[r0], g1 = graph_ids[r1];

        float acc[8][4];
        #pragma unroll
        for (int nt = 0; nt < 8; nt++) {
            float b0 = sb[nt*8 + 2*c], b1 = sb[nt*8 + 2*c + 1];
            acc[nt][0] = b0; acc[nt][1] = b1; acc[nt][2] = b0; acc[nt][3] = b1;
        }

        #pragma unroll
        for (int kk = 0; kk < 8; kk++) {
            int k0 = kk * 16;
            const __half* src = (kk < 4) ? fh : fa;
            int koff = (kk < 4) ? k0 : k0 - HID;
            u32 a0 = *(const u32*)(src + r0*HID + koff + 2*c);
            u32 a1 = *(const u32*)(src + r1*HID + koff + 2*c);
            u32 a2 = *(const u32*)(src + r0*HID + koff + 8 + 2*c);
            u32 a3 = *(const u32*)(src + r1*HID + koff + 8 + 2*c);
            #pragma unroll
            for (int nt = 0; nt < 8; nt++) {
                int n = nt*8 + gid;
                u32 b0 = *(const u32*)&sWt[n * WS + k0 + 2*c];
                u32 b1 = *(const u32*)&sWt[n * WS + k0 + 8 + 2*c];
                mma16816(acc[nt][0], acc[nt][1], acc[nt][2], acc[nt][3],
                         a0, a1, a2, a3, b0, b1);
            }
        }

        #pragma unroll
        for (int nt = 0; nt < 8; nt++) {
            int col = nt*8 + 2*c;
            red2(&g_hg[g0*HID + col], fmaxf(acc[nt][0],0.f), fmaxf(acc[nt][1],0.f));
            red2(&g_hg[g1*HID + col], fmaxf(acc[nt][2],0.f), fmaxf(acc[nt][3],0.f));
        }
    }
}

// scorer
__global__ void k_final(const float* __restrict__ Ws1, const float* __restrict__ bs1,
                        const float* __restrict__ Ws2, const float* __restrict__ bs2,
                        float* __restrict__ out) {
    __shared__ float sW[HID * HID];
    int tid = threadIdx.x;
    for (int i = tid; i < HID * HID; i += 64) sW[i] = Ws1[i];
    __syncthreads();

    int g = blockIdx.x * 64 + tid;
    if (g >= Bb) return;

    float cv = (float)(g_glast[g] - g_gfirst[g]);
    float inv = 1.0f / fmaxf(cv, 1.0f);
    float hv[HID];
    #pragma unroll
    for (int k = 0; k < HID; k++) hv[k] = g_hg[g * HID + k] * inv;

    float s = bs2[0];
    #pragma unroll 1
    for (int j = 0; j < HID; j++) {
        float t = bs1[j];
        #pragma unroll
        for (int k = 0; k < HID; k++) t += hv[k] * sW[k * HID + j];
        s += fmaxf(t, 0.f) * Ws2[j];
    }
    out[g] = s;
}

// ---------------- launcher ----------------
extern "C" void kernel_launch(void* const* d_in, const int* in_sizes, int n_in,
                              void* d_out, int out_size) {
    const int*    node_ids  = (const int*)   d_in[0];
    const int*    src       = (const int*)   d_in[1];
    const int*    dst       = (const int*)   d_in[2];
    const int*    graph_ids = (const int*)   d_in[3];
    const float4* emb       = (const float4*)d_in[4];
    const float*  W_self1   = (const float*) d_in[5];
    const float*  W_neigh1  = (const float*) d_in[6];
    const float*  b1        = (const float*) d_in[7];
    const float*  W_self2   = (const float*) d_in[8];
    const float*  W_neigh2  = (const float*) d_in[9];
    const float*  b2        = (const float*) d_in[10];
    const float*  Ws1       = (const float*) d_in[11];
    const float*  bs1       = (const float*) d_in[12];
    const float*  Ws2       = (const float*) d_in[13];
    const float*  bs2       = (const float*) d_in[14];
    float* out = (float*)d_out;

    k_deg        <<<(Ee + 255) / 256, 256>>>(dst, graph_ids);           // 0
    k_scan       <<<NT, 256>>>();                                       // 1
    k_fill_gather<<<(Ee + 255) / 256, 256>>>(src, dst, node_ids, emb);  // 2
    k_agg1       <<<(Nn * 4 + 255) / 256, 256>>>();                     // 3
    k_update1_mma<<<NUB, 256>>>(W_self1, W_neigh1, b1);                 // 4
    k_agg2       <<<(Nn * 8 + 255) / 256, 256>>>();                     // 5
    k_update2_mma<<<NUB, 256>>>(W_self2, W_neigh2, b2, graph_ids);      // 6
    k_final      <<<(Bb + 63) / 64, 64>>>(Ws1, bs1, Ws2, bs2, out);     // 7
}